// round 1
// baseline (speedup 1.0000x reference)
#include <cuda_runtime.h>
#include <math.h>

// ---------------- problem constants ----------------
#define BATCH   2
#define SEQ     8192
#define DMODEL  512
#define NH      8
#define DH      64
#define BHEADS  16              // BATCH * NH
#define BNROWS  16384           // BATCH * SEQ
#define QKVN    1536            // 3 * NH * DH
#define HID     1365            // int(512*4*2/3)
#define HID2    2730
#define WSIZE   512             // local attention window

// ---------------- scratch buffers (device globals, no allocation) ----------------
__device__ float g_h   [(size_t)BNROWS * DMODEL];   // LN output (reused twice)
__device__ float g_qkv [(size_t)BNROWS * QKVN];
__device__ float g_q   [(size_t)BHEADS * SEQ * DH];
__device__ float g_k   [(size_t)BHEADS * SEQ * DH];
__device__ float g_v   [(size_t)BHEADS * SEQ * DH];
__device__ float g_o   [(size_t)BNROWS * DMODEL];
__device__ float g_x1  [(size_t)BNROWS * DMODEL];
__device__ float g_u   [(size_t)BNROWS * HID2];
__device__ float g_gate[(size_t)BNROWS * HID];

// ---------------- LayerNorm (one block per row of 512) ----------------
__global__ void ln_kernel(const float* __restrict__ x,
                          const float* __restrict__ gamma,
                          const float* __restrict__ beta,
                          float* __restrict__ out)
{
    int row = blockIdx.x;
    int tid = threadIdx.x;                  // 256 threads, 2 elems each
    const float* xr = x + (size_t)row * DMODEL;
    float v0 = xr[tid];
    float v1 = xr[tid + 256];
    float s  = v0 + v1;
    float ss = v0 * v0 + v1 * v1;

    __shared__ float shs[8], shss[8];
    #pragma unroll
    for (int o = 16; o > 0; o >>= 1) {
        s  += __shfl_down_sync(0xffffffffu, s,  o);
        ss += __shfl_down_sync(0xffffffffu, ss, o);
    }
    if ((tid & 31) == 0) { shs[tid >> 5] = s; shss[tid >> 5] = ss; }
    __syncthreads();
    if (tid < 8) {
        s = shs[tid]; ss = shss[tid];
        #pragma unroll
        for (int o = 4; o > 0; o >>= 1) {
            s  += __shfl_down_sync(0xffu, s,  o);
            ss += __shfl_down_sync(0xffu, ss, o);
        }
        if (tid == 0) { shs[0] = s; shss[0] = ss; }
    }
    __syncthreads();
    float mean = shs[0]  * (1.0f / DMODEL);
    float var  = shss[0] * (1.0f / DMODEL) - mean * mean;
    float inv  = rsqrtf(var + 1e-5f);
    float* outr = out + (size_t)row * DMODEL;
    outr[tid]       = (v0 - mean) * inv * gamma[tid]       + beta[tid];
    outr[tid + 256] = (v1 - mean) * inv * gamma[tid + 256] + beta[tid + 256];
}

// ---------------- generic fp32 GEMM: C = A(MxK) @ B(KxN) [+bias][+res] ----------------
// 128x128 tile, BK=16, 256 threads, 8x8 microtile per thread.
template<bool HAS_BIAS, bool HAS_RES>
__global__ void __launch_bounds__(256)
gemm128(const float* __restrict__ A, const float* __restrict__ B,
        const float* __restrict__ bias, const float* __restrict__ res,
        float* __restrict__ C, int M, int N, int K)
{
    __shared__ float As[16][132];
    __shared__ float Bs[16][132];
    int tid = threadIdx.x;
    int tx = tid & 15, ty = tid >> 4;
    int m0 = blockIdx.y * 128, n0 = blockIdx.x * 128;

    float acc[8][8];
    #pragma unroll
    for (int i = 0; i < 8; i++)
        #pragma unroll
        for (int j = 0; j < 8; j++) acc[i][j] = 0.0f;

    for (int k0 = 0; k0 < K; k0 += 16) {
        // A tile 128x16 -> As[k][m]
        #pragma unroll
        for (int i = 0; i < 8; i++) {
            int idx = i * 256 + tid;
            int m = idx >> 4, k = idx & 15;
            float v = 0.0f;
            if (k0 + k < K) v = A[(size_t)(m0 + m) * K + k0 + k];
            As[k][m] = v;
        }
        // B tile 16x128 -> Bs[k][n]
        #pragma unroll
        for (int i = 0; i < 8; i++) {
            int idx = i * 256 + tid;
            int k = idx >> 7, n = idx & 127;
            float v = 0.0f;
            if ((k0 + k < K) && (n0 + n < N)) v = B[(size_t)(k0 + k) * N + n0 + n];
            Bs[k][n] = v;
        }
        __syncthreads();
        #pragma unroll
        for (int k = 0; k < 16; k++) {
            float a[8], bb[8];
            *(float4*)&a[0]  = *(const float4*)&As[k][ty * 4];
            *(float4*)&a[4]  = *(const float4*)&As[k][64 + ty * 4];
            *(float4*)&bb[0] = *(const float4*)&Bs[k][tx * 4];
            *(float4*)&bb[4] = *(const float4*)&Bs[k][64 + tx * 4];
            #pragma unroll
            for (int i = 0; i < 8; i++)
                #pragma unroll
                for (int j = 0; j < 8; j++)
                    acc[i][j] = fmaf(a[i], bb[j], acc[i][j]);
        }
        __syncthreads();
    }

    // epilogue (M is always a multiple of 128 here; guard N only)
    #pragma unroll
    for (int i = 0; i < 8; i++) {
        int r = m0 + ((i < 4) ? (ty * 4 + i) : (64 + ty * 4 + i - 4));
        #pragma unroll
        for (int j = 0; j < 8; j++) {
            int c = n0 + ((j < 4) ? (tx * 4 + j) : (64 + tx * 4 + j - 4));
            if (c < N) {
                float v = acc[i][j];
                if (HAS_BIAS) v += bias[c];
                if (HAS_RES)  v += res[(size_t)r * N + c];
                C[(size_t)r * N + c] = v;
            }
        }
    }
}

// ---------------- QKV split + l2norm + scale + rotary xpos ----------------
// one warp per (b, n, h); lane handles dims (lane, lane+32)
__global__ void qkv_rotary_kernel(const float* __restrict__ q_scale,
                                  const float* __restrict__ k_scale)
{
    int lane = threadIdx.x & 31;
    int warp = threadIdx.x >> 5;
    long task = (long)blockIdx.x * 4 + warp;     // 0 .. BATCH*SEQ*NH-1
    int b = (int)(task / ((long)SEQ * NH));
    long rem = task - (long)b * SEQ * NH;
    int n = (int)(rem / NH);
    int h = (int)(rem - (long)n * NH);

    size_t base = ((size_t)b * SEQ + n) * QKVN + (size_t)h * DH;
    float q0 = g_qkv[base + lane],        q1 = g_qkv[base + 32 + lane];
    float k0 = g_qkv[base + 512 + lane],  k1 = g_qkv[base + 512 + 32 + lane];
    float v0 = g_qkv[base + 1024 + lane], v1 = g_qkv[base + 1024 + 32 + lane];

    float sq = q0 * q0 + q1 * q1;
    float sk = k0 * k0 + k1 * k1;
    #pragma unroll
    for (int o = 16; o > 0; o >>= 1) {
        sq += __shfl_xor_sync(0xffffffffu, sq, o);
        sk += __shfl_xor_sync(0xffffffffu, sk, o);
    }
    float qinv = 1.0f / fmaxf(sqrtf(sq), 1e-12f);
    float kinv = 1.0f / fmaxf(sqrtf(sk), 1e-12f);
    q0 = q0 * qinv * q_scale[lane];
    q1 = q1 * qinv * q_scale[lane + 32];
    k0 = k0 * kinv * k_scale[lane];
    k1 = k1 * kinv * k_scale[lane + 32];

    // rotary xpos: dim=64, half-dim index j = lane for both halves
    float t    = (float)n;
    float invf = powf(10000.0f, -(float)lane / 32.0f);
    float fr   = t * invf;
    float c = cosf(fr), s = sinf(fr);
    float sv = (2.0f * (float)lane + 0.4f * 64.0f) / (1.4f * 64.0f);
    float pw = (t - (float)(SEQ / 2)) / (float)(WSIZE / 2);
    float xs = powf(sv, pw);
    float ixs = 1.0f / xs;

    float qo0 = (q0 * c - q1 * s) * xs;
    float qo1 = (q1 * c + q0 * s) * xs;
    float ko0 = (k0 * c - k1 * s) * ixs;
    float ko1 = (k1 * c + k0 * s) * ixs;

    size_t obase = ((size_t)(b * NH + h) * SEQ + n) * DH;
    g_q[obase + lane] = qo0;  g_q[obase + 32 + lane] = qo1;
    g_k[obase + lane] = ko0;  g_k[obase + 32 + lane] = ko1;
    g_v[obase + lane] = v0;   g_v[obase + 32 + lane] = v1;
}

// ---------------- local windowed attention ----------------
// One thread per query (128 queries/block). Keys: the 1024-key look-around
// range, streamed through smem in 64-key tiles.
// |sim| <= QK_SCALE=8 analytically (l2norm'd q/k, xpos ratio <= 1), so no
// online max is needed: exp(s) is bounded by e^8.
__global__ void __launch_bounds__(128) attn_kernel()
{
    __shared__ float Ks[64][64];
    __shared__ float Vs[64][64];
    int tid = threadIdx.x;
    int qb  = blockIdx.x;          // 0..63 (SEQ/128)
    int bh  = blockIdx.y;          // 0..15
    int t   = qb * 128 + tid;      // global query position
    int w   = t >> 9;              // window index (512 per window)
    int ii  = t & 511;             // position within window
    int ii0 = (qb * 128) & 511;    // block-uniform
    int j0  = (w - 1) * WSIZE;     // global pos of key slot 0

    float q[64];
    size_t qoff = ((size_t)bh * SEQ + t) * DH;
    #pragma unroll
    for (int i = 0; i < 16; i++)
        *(float4*)&q[i * 4] = *(const float4*)&g_q[qoff + i * 4];

    float acc[64];
    #pragma unroll
    for (int d = 0; d < 64; d++) acc[d] = 0.0f;
    float denom = 0.0f;

    for (int kt = 0; kt < 16; kt++) {
        int jjb = kt * 64;
        // block-uniform tile skip: allowed jj range for this block is [ii0, ii0+639]
        if (jjb + 63 < ii0) continue;
        if (jjb > ii0 + 639) continue;
        if (w == 0 && jjb + 63 < 512) continue;   // padding keys (j == -1)

        // cooperative tile load (4096 floats each for K and V)
        #pragma unroll
        for (int i = 0; i < 8; i++) {
            int l  = i * 128 + tid;       // float4 index
            int kk = l >> 4, d4 = l & 15;
            int jg = j0 + jjb + kk;
            float4 kv = make_float4(0.f, 0.f, 0.f, 0.f);
            float4 vv = make_float4(0.f, 0.f, 0.f, 0.f);
            if (jg >= 0) {
                size_t off = ((size_t)bh * SEQ + jg) * DH + d4 * 4;
                kv = *(const float4*)&g_k[off];
                vv = *(const float4*)&g_v[off];
            }
            *(float4*)&Ks[kk][d4 * 4] = kv;
            *(float4*)&Vs[kk][d4 * 4] = vv;
        }
        __syncthreads();

        for (int kk = 0; kk < 64; kk++) {
            int jj = jjb + kk;
            bool ok = (jj >= ii) && (jj <= ii + 512) && (w > 0 || jj >= 512);
            if (!ok) continue;
            float dot = 0.0f;
            #pragma unroll
            for (int d = 0; d < 64; d++) dot = fmaf(q[d], Ks[kk][d], dot);
            float p = expf(8.0f * dot);
            denom += p;
            #pragma unroll
            for (int d = 0; d < 64; d++) acc[d] = fmaf(p, Vs[kk][d], acc[d]);
        }
        __syncthreads();
    }

    float dinv = 1.0f / denom;
    int b = bh >> 3, h = bh & 7;
    size_t obase = ((size_t)b * SEQ + t) * DMODEL + (size_t)h * DH;
    #pragma unroll
    for (int d = 0; d < 64; d++) g_o[obase + d] = acc[d] * dinv;
}

// ---------------- gated GELU (exact erf) ----------------
__global__ void geglu_kernel()
{
    long idx = (long)blockIdx.x * blockDim.x + threadIdx.x;
    long total = (long)BNROWS * HID;
    if (idx >= total) return;
    long r = idx / HID;
    int  c = (int)(idx - r * HID);
    float a  = g_u[r * HID2 + c];
    float gt = g_u[r * HID2 + HID + c];
    float ge = 0.5f * gt * (1.0f + erff(gt * 0.70710678118654752f));
    g_gate[idx] = a * ge;
}

// ---------------- launch ----------------
extern "C" void kernel_launch(void* const* d_in, const int* in_sizes, int n_in,
                              void* d_out, int out_size)
{
    const float* x     = (const float*)d_in[0];
    const float* ln1g  = (const float*)d_in[1];
    const float* ln1b  = (const float*)d_in[2];
    const float* Wqkv  = (const float*)d_in[3];
    const float* qsc   = (const float*)d_in[4];
    const float* ksc   = (const float*)d_in[5];
    const float* Wout  = (const float*)d_in[6];
    const float* ln2g  = (const float*)d_in[7];
    const float* ln2b  = (const float*)d_in[8];
    const float* W1    = (const float*)d_in[9];
    const float* b1    = (const float*)d_in[10];
    const float* W2    = (const float*)d_in[11];
    const float* b2    = (const float*)d_in[12];
    float* out = (float*)d_out;

    float *ph, *pqkv, *po, *px1, *pu, *pg;
    cudaGetSymbolAddress((void**)&ph,   g_h);
    cudaGetSymbolAddress((void**)&pqkv, g_qkv);
    cudaGetSymbolAddress((void**)&po,   g_o);
    cudaGetSymbolAddress((void**)&px1,  g_x1);
    cudaGetSymbolAddress((void**)&pu,   g_u);
    cudaGetSymbolAddress((void**)&pg,   g_gate);

    // 1) LN1
    ln_kernel<<<BNROWS, 256>>>(x, ln1g, ln1b, ph);
    // 2) QKV GEMM: (16384x512) @ (512x1536)
    gemm128<false, false><<<dim3(QKVN / 128, BNROWS / 128), 256>>>(
        ph, Wqkv, nullptr, nullptr, pqkv, BNROWS, QKVN, DMODEL);
    // 3) split + l2norm + rotary xpos
    qkv_rotary_kernel<<<(BATCH * SEQ * NH) / 4, 128>>>(qsc, ksc);
    // 4) local attention
    attn_kernel<<<dim3(SEQ / 128, BHEADS), 128>>>();
    // 5) out projection + residual: x1 = x + o @ Wout
    gemm128<false, true><<<dim3(DMODEL / 128, BNROWS / 128), 256>>>(
        po, Wout, nullptr, x, px1, BNROWS, DMODEL, DMODEL);
    // 6) LN2
    ln_kernel<<<BNROWS, 256>>>(px1, ln2g, ln2b, ph);
    // 7) FF1: (16384x512) @ (512x2730) + b1
    gemm128<true, false><<<dim3((HID2 + 127) / 128, BNROWS / 128), 256>>>(
        ph, W1, b1, nullptr, pu, BNROWS, HID2, DMODEL);
    // 8) gated gelu
    {
        long total = (long)BNROWS * HID;
        int blocks = (int)((total + 255) / 256);
        geglu_kernel<<<blocks, 256>>>();
    }
    // 9) FF2 + b2 + residual -> out
    gemm128<true, true><<<dim3(DMODEL / 128, BNROWS / 128), 256>>>(
        pg, W2, b2, px1, out, BNROWS, DMODEL, HID);
}

// round 2
// speedup vs baseline: 1.7048x; 1.7048x over previous
#include <cuda_runtime.h>
#include <math.h>

// ---------------- problem constants ----------------
#define BATCH   2
#define SEQ     8192
#define DMODEL  512
#define NH      8
#define DH      64
#define BHEADS  16              // BATCH * NH
#define BNROWS  16384           // BATCH * SEQ
#define QKVN    1536            // 3 * NH * DH
#define HID     1365            // int(512*4*2/3)
#define HID2    2730
#define WSIZE   512             // local attention window

// ---------------- scratch buffers ----------------
__device__ float g_h   [(size_t)BNROWS * DMODEL];
__device__ float g_qkv [(size_t)BNROWS * QKVN];
__device__ float g_q   [(size_t)BHEADS * SEQ * DH];
__device__ float g_k   [(size_t)BHEADS * SEQ * DH];
__device__ float g_v   [(size_t)BHEADS * SEQ * DH];
__device__ float g_o   [(size_t)BNROWS * DMODEL];
__device__ float g_x1  [(size_t)BNROWS * DMODEL];
__device__ float g_u   [(size_t)BNROWS * HID2];
__device__ float g_gate[(size_t)BNROWS * HID];

// ---------------- helpers ----------------
__device__ __forceinline__ unsigned f2tf32(float f) {
    unsigned u;
    asm("cvt.rna.tf32.f32 %0, %1;" : "=r"(u) : "f"(f));
    return u;
}

__device__ __forceinline__ void mma_tf32(float c[4], const unsigned a[4], const unsigned b[2]) {
    asm volatile(
        "mma.sync.aligned.m16n8k8.row.col.f32.tf32.tf32.f32 "
        "{%0,%1,%2,%3}, {%4,%5,%6,%7}, {%8,%9}, {%0,%1,%2,%3};"
        : "+f"(c[0]), "+f"(c[1]), "+f"(c[2]), "+f"(c[3])
        : "r"(a[0]), "r"(a[1]), "r"(a[2]), "r"(a[3]), "r"(b[0]), "r"(b[1]));
}

// ---------------- LayerNorm ----------------
__global__ void ln_kernel(const float* __restrict__ x,
                          const float* __restrict__ gamma,
                          const float* __restrict__ beta,
                          float* __restrict__ out)
{
    int row = blockIdx.x;
    int tid = threadIdx.x;                  // 256 threads, 2 elems each
    const float* xr = x + (size_t)row * DMODEL;
    float v0 = xr[tid];
    float v1 = xr[tid + 256];
    float s  = v0 + v1;
    float ss = v0 * v0 + v1 * v1;

    __shared__ float shs[8], shss[8];
    #pragma unroll
    for (int o = 16; o > 0; o >>= 1) {
        s  += __shfl_down_sync(0xffffffffu, s,  o);
        ss += __shfl_down_sync(0xffffffffu, ss, o);
    }
    if ((tid & 31) == 0) { shs[tid >> 5] = s; shss[tid >> 5] = ss; }
    __syncthreads();
    if (tid < 8) {
        s = shs[tid]; ss = shss[tid];
        #pragma unroll
        for (int o = 4; o > 0; o >>= 1) {
            s  += __shfl_down_sync(0xffu, s,  o);
            ss += __shfl_down_sync(0xffu, ss, o);
        }
        if (tid == 0) { shs[0] = s; shss[0] = ss; }
    }
    __syncthreads();
    float mean = shs[0]  * (1.0f / DMODEL);
    float var  = shss[0] * (1.0f / DMODEL) - mean * mean;
    float inv  = rsqrtf(var + 1e-5f);
    float* outr = out + (size_t)row * DMODEL;
    outr[tid]       = (v0 - mean) * inv * gamma[tid]       + beta[tid];
    outr[tid + 256] = (v1 - mean) * inv * gamma[tid + 256] + beta[tid + 256];
}

// ---------------- tf32 tensor-core GEMM ----------------
// C(MxN) = A(MxK) @ B(KxN) [+bias][+res]; 128x128 CTA tile, BK=32,
// 8 warps (2m x 4n), each warp 64x32 via m16n8k8 tf32 mma.
template<bool HAS_BIAS, bool HAS_RES>
__global__ void __launch_bounds__(256, 2)
gemm_tf32(const float* __restrict__ A, const float* __restrict__ B,
          const float* __restrict__ bias, const float* __restrict__ res,
          float* __restrict__ C, int M, int N, int K)
{
    __shared__ unsigned As[128][36];   // padded: fragment loads conflict-free
    __shared__ unsigned Bs[32][136];

    int tid  = threadIdx.x;
    int lane = tid & 31;
    int wid  = tid >> 5;
    int g  = lane >> 2;        // 0..7
    int tg = lane & 3;         // 0..3
    int wm = (wid & 1) * 64;   // warp m offset
    int wn = (wid >> 1) * 32;  // warp n offset
    int m0 = blockIdx.y * 128, n0 = blockIdx.x * 128;

    float c[4][4][4];
    #pragma unroll
    for (int i = 0; i < 4; i++)
        #pragma unroll
        for (int j = 0; j < 4; j++)
            #pragma unroll
            for (int l = 0; l < 4; l++) c[i][j][l] = 0.0f;

    for (int k0 = 0; k0 < K; k0 += 32) {
        // stage A tile (128x32) with tf32 rounding
        #pragma unroll
        for (int i = 0; i < 16; i++) {
            int idx = i * 256 + tid;
            int r = idx >> 5, cc = idx & 31;
            float v = (k0 + cc < K) ? A[(size_t)(m0 + r) * K + k0 + cc] : 0.0f;
            As[r][cc] = f2tf32(v);
        }
        // stage B tile (32x128)
        #pragma unroll
        for (int i = 0; i < 16; i++) {
            int idx = i * 256 + tid;
            int r = idx >> 7, cc = idx & 127;
            float v = (k0 + r < K && n0 + cc < N)
                      ? B[(size_t)(k0 + r) * N + n0 + cc] : 0.0f;
            Bs[r][cc] = f2tf32(v);
        }
        __syncthreads();

        #pragma unroll
        for (int ks = 0; ks < 4; ks++) {
            unsigned a[4][4], b[4][2];
            #pragma unroll
            for (int mf = 0; mf < 4; mf++) {
                int row = wm + mf * 16 + g;
                int col = ks * 8 + tg;
                a[mf][0] = As[row][col];
                a[mf][1] = As[row + 8][col];
                a[mf][2] = As[row][col + 4];
                a[mf][3] = As[row + 8][col + 4];
            }
            #pragma unroll
            for (int nf = 0; nf < 4; nf++) {
                int col = wn + nf * 8 + g;
                b[nf][0] = Bs[ks * 8 + tg][col];
                b[nf][1] = Bs[ks * 8 + tg + 4][col];
            }
            #pragma unroll
            for (int mf = 0; mf < 4; mf++)
                #pragma unroll
                for (int nf = 0; nf < 4; nf++)
                    mma_tf32(c[mf][nf], a[mf], b[nf]);
        }
        __syncthreads();
    }

    // epilogue
    #pragma unroll
    for (int mf = 0; mf < 4; mf++) {
        int r0 = m0 + wm + mf * 16 + g;
        #pragma unroll
        for (int nf = 0; nf < 4; nf++) {
            int cc = n0 + wn + nf * 8 + 2 * tg;
            #pragma unroll
            for (int half = 0; half < 2; half++) {
                int r = r0 + half * 8;
                #pragma unroll
                for (int jj = 0; jj < 2; jj++) {
                    int col = cc + jj;
                    if (col < N) {
                        float v = c[mf][nf][half * 2 + jj];
                        if (HAS_BIAS) v += bias[col];
                        if (HAS_RES)  v += res[(size_t)r * N + col];
                        C[(size_t)r * N + col] = v;
                    }
                }
            }
        }
    }
}

// ---------------- QKV split + l2norm + scale + rotary xpos ----------------
__global__ void qkv_rotary_kernel(const float* __restrict__ q_scale,
                                  const float* __restrict__ k_scale)
{
    int lane = threadIdx.x & 31;
    int warp = threadIdx.x >> 5;
    long task = (long)blockIdx.x * 4 + warp;
    int b = (int)(task / ((long)SEQ * NH));
    long rem = task - (long)b * SEQ * NH;
    int n = (int)(rem / NH);
    int h = (int)(rem - (long)n * NH);

    size_t base = ((size_t)b * SEQ + n) * QKVN + (size_t)h * DH;
    float q0 = g_qkv[base + lane],        q1 = g_qkv[base + 32 + lane];
    float k0 = g_qkv[base + 512 + lane],  k1 = g_qkv[base + 512 + 32 + lane];
    float v0 = g_qkv[base + 1024 + lane], v1 = g_qkv[base + 1024 + 32 + lane];

    float sq = q0 * q0 + q1 * q1;
    float sk = k0 * k0 + k1 * k1;
    #pragma unroll
    for (int o = 16; o > 0; o >>= 1) {
        sq += __shfl_xor_sync(0xffffffffu, sq, o);
        sk += __shfl_xor_sync(0xffffffffu, sk, o);
    }
    float qinv = 1.0f / fmaxf(sqrtf(sq), 1e-12f);
    float kinv = 1.0f / fmaxf(sqrtf(sk), 1e-12f);
    q0 = q0 * qinv * q_scale[lane];
    q1 = q1 * qinv * q_scale[lane + 32];
    k0 = k0 * kinv * k_scale[lane];
    k1 = k1 * kinv * k_scale[lane + 32];

    float t    = (float)n;
    float invf = powf(10000.0f, -(float)lane / 32.0f);
    float fr   = t * invf;
    float cs = cosf(fr), sn = sinf(fr);
    float sv = (2.0f * (float)lane + 0.4f * 64.0f) / (1.4f * 64.0f);
    float pw = (t - (float)(SEQ / 2)) / (float)(WSIZE / 2);
    float xs = powf(sv, pw);
    float ixs = 1.0f / xs;

    float qo0 = (q0 * cs - q1 * sn) * xs;
    float qo1 = (q1 * cs + q0 * sn) * xs;
    float ko0 = (k0 * cs - k1 * sn) * ixs;
    float ko1 = (k1 * cs + k0 * sn) * ixs;

    size_t obase = ((size_t)(b * NH + h) * SEQ + n) * DH;
    g_q[obase + lane] = qo0;  g_q[obase + 32 + lane] = qo1;
    g_k[obase + lane] = ko0;  g_k[obase + 32 + lane] = ko1;
    g_v[obase + lane] = v0;   g_v[obase + 32 + lane] = v1;
}

// ---------------- local windowed attention ----------------
// 2 threads per query: dims split 0-31 / 32-63. Halves combined with one
// shfl_xor(1). Odd half stored at +36 floats in smem rows (stride 72) so
// paired float4 reads hit disjoint banks. |sim|<=8 analytically -> no
// online-max needed.
__global__ void __launch_bounds__(256) attn_kernel()
{
    __shared__ float Ks[64][72];
    __shared__ float Vs[64][72];
    int tid  = threadIdx.x;
    int qi   = tid >> 1;
    int half = tid & 1;
    int qb   = blockIdx.x;          // 0..63
    int bh   = blockIdx.y;          // 0..15
    int t    = qb * 128 + qi;
    int w    = t >> 9;
    int ii   = t & 511;
    int ii0  = (qb * 128) & 511;
    int j0   = (w - 1) * WSIZE;
    int colbase = half * 36;

    float4 q[8];
    size_t qoff = ((size_t)bh * SEQ + t) * DH + half * 32;
    #pragma unroll
    for (int i = 0; i < 8; i++)
        q[i] = *(const float4*)&g_q[qoff + i * 4];

    float4 acc[8];
    #pragma unroll
    for (int i = 0; i < 8; i++) acc[i] = make_float4(0.f, 0.f, 0.f, 0.f);
    float denom = 0.0f;

    for (int kt = 0; kt < 16; kt++) {
        int jjb = kt * 64;
        if (jjb + 63 < ii0) continue;
        if (jjb > ii0 + 639) continue;
        if (w == 0 && jjb + 63 < 512) continue;

        #pragma unroll
        for (int i = 0; i < 4; i++) {
            int l  = i * 256 + tid;
            int kk = l >> 4, d4 = l & 15;
            int col = d4 * 4 + (d4 >= 8 ? 4 : 0);
            int jg = j0 + jjb + kk;
            float4 kv = make_float4(0.f, 0.f, 0.f, 0.f);
            float4 vv = make_float4(0.f, 0.f, 0.f, 0.f);
            if (jg >= 0) {
                size_t off = ((size_t)bh * SEQ + jg) * DH + d4 * 4;
                kv = *(const float4*)&g_k[off];
                vv = *(const float4*)&g_v[off];
            }
            *(float4*)&Ks[kk][col] = kv;
            *(float4*)&Vs[kk][col] = vv;
        }
        __syncthreads();

        for (int kk = 0; kk < 64; kk++) {
            int jj = jjb + kk;
            bool ok = (jj >= ii) && (jj <= ii + 512) && (w > 0 || jj >= 512);
            float partial = 0.0f;
            const float* kr = &Ks[kk][colbase];
            #pragma unroll
            for (int i = 0; i < 8; i++) {
                float4 kv = *(const float4*)&kr[i * 4];
                partial = fmaf(q[i].x, kv.x, partial);
                partial = fmaf(q[i].y, kv.y, partial);
                partial = fmaf(q[i].z, kv.z, partial);
                partial = fmaf(q[i].w, kv.w, partial);
            }
            float full = partial + __shfl_xor_sync(0xffffffffu, partial, 1);
            float p = ok ? expf(8.0f * full) : 0.0f;
            denom += p;
            const float* vr = &Vs[kk][colbase];
            #pragma unroll
            for (int i = 0; i < 8; i++) {
                float4 vv = *(const float4*)&vr[i * 4];
                acc[i].x = fmaf(p, vv.x, acc[i].x);
                acc[i].y = fmaf(p, vv.y, acc[i].y);
                acc[i].z = fmaf(p, vv.z, acc[i].z);
                acc[i].w = fmaf(p, vv.w, acc[i].w);
            }
        }
        __syncthreads();
    }

    float dinv = 1.0f / denom;
    int b = bh >> 3, h = bh & 7;
    size_t obase = ((size_t)b * SEQ + t) * DMODEL + (size_t)h * DH + half * 32;
    #pragma unroll
    for (int i = 0; i < 8; i++) {
        float4 o = make_float4(acc[i].x * dinv, acc[i].y * dinv,
                               acc[i].z * dinv, acc[i].w * dinv);
        *(float4*)&g_o[obase + i * 4] = o;
    }
}

// ---------------- gated GELU ----------------
__global__ void geglu_kernel()
{
    long idx = (long)blockIdx.x * blockDim.x + threadIdx.x;
    long total = (long)BNROWS * HID;
    if (idx >= total) return;
    long r = idx / HID;
    int  c = (int)(idx - r * HID);
    float a  = g_u[r * HID2 + c];
    float gt = g_u[r * HID2 + HID + c];
    float ge = 0.5f * gt * (1.0f + erff(gt * 0.70710678118654752f));
    g_gate[idx] = a * ge;
}

// ---------------- launch ----------------
extern "C" void kernel_launch(void* const* d_in, const int* in_sizes, int n_in,
                              void* d_out, int out_size)
{
    const float* x     = (const float*)d_in[0];
    const float* ln1g  = (const float*)d_in[1];
    const float* ln1b  = (const float*)d_in[2];
    const float* Wqkv  = (const float*)d_in[3];
    const float* qsc   = (const float*)d_in[4];
    const float* ksc   = (const float*)d_in[5];
    const float* Wout  = (const float*)d_in[6];
    const float* ln2g  = (const float*)d_in[7];
    const float* ln2b  = (const float*)d_in[8];
    const float* W1    = (const float*)d_in[9];
    const float* b1    = (const float*)d_in[10];
    const float* W2    = (const float*)d_in[11];
    const float* b2    = (const float*)d_in[12];
    float* out = (float*)d_out;

    float *ph, *pqkv, *po, *px1, *pu, *pg;
    cudaGetSymbolAddress((void**)&ph,   g_h);
    cudaGetSymbolAddress((void**)&pqkv, g_qkv);
    cudaGetSymbolAddress((void**)&po,   g_o);
    cudaGetSymbolAddress((void**)&px1,  g_x1);
    cudaGetSymbolAddress((void**)&pu,   g_u);
    cudaGetSymbolAddress((void**)&pg,   g_gate);

    // 1) LN1
    ln_kernel<<<BNROWS, 256>>>(x, ln1g, ln1b, ph);
    // 2) QKV GEMM
    gemm_tf32<false, false><<<dim3(QKVN / 128, BNROWS / 128), 256>>>(
        ph, Wqkv, nullptr, nullptr, pqkv, BNROWS, QKVN, DMODEL);
    // 3) split + l2norm + rotary xpos
    qkv_rotary_kernel<<<(BATCH * SEQ * NH) / 4, 128>>>(qsc, ksc);
    // 4) local attention
    attn_kernel<<<dim3(SEQ / 128, BHEADS), 256>>>();
    // 5) out projection + residual
    gemm_tf32<false, true><<<dim3(DMODEL / 128, BNROWS / 128), 256>>>(
        po, Wout, nullptr, x, px1, BNROWS, DMODEL, DMODEL);
    // 6) LN2
    ln_kernel<<<BNROWS, 256>>>(px1, ln2g, ln2b, ph);
    // 7) FF1
    gemm_tf32<true, false><<<dim3((HID2 + 127) / 128, BNROWS / 128), 256>>>(
        ph, W1, b1, nullptr, pu, BNROWS, HID2, DMODEL);
    // 8) gated gelu
    {
        long total = (long)BNROWS * HID;
        int blocks = (int)((total + 255) / 256);
        geglu_kernel<<<blocks, 256>>>();
    }
    // 9) FF2 + residual -> out
    gemm_tf32<true, true><<<dim3(DMODEL / 128, BNROWS / 128), 256>>>(
        pg, W2, b2, px1, out, BNROWS, DMODEL, HID);
}

// round 4
// speedup vs baseline: 3.1290x; 1.8354x over previous
#include <cuda_runtime.h>
#include <math.h>

// ---------------- problem constants ----------------
#define BATCH   2
#define SEQ     8192
#define DMODEL  512
#define NH      8
#define DH      64
#define BHEADS  16
#define BNROWS  16384
#define QKVN    1536
#define HID     1365
#define HID2    2730
#define HIDP    1368   // padded gate stride: 1368*4 bytes % 16 == 0
#define W1P     2732   // padded W1 stride:   2732*4 bytes % 16 == 0
#define WSIZE   512

// ---------------- scratch buffers ----------------
__device__ float g_h   [(size_t)BNROWS * DMODEL];
__device__ float g_qkv [(size_t)BNROWS * QKVN];
__device__ float g_q   [(size_t)BHEADS * SEQ * DH];
__device__ float g_k   [(size_t)BHEADS * SEQ * DH];
__device__ float g_v   [(size_t)BHEADS * SEQ * DH];
__device__ float g_o   [(size_t)BNROWS * DMODEL];
__device__ float g_x1  [(size_t)BNROWS * DMODEL];
__device__ float g_u   [(size_t)BNROWS * HID2];
__device__ float g_gate[(size_t)BNROWS * HIDP];
__device__ float g_W1p [(size_t)DMODEL * W1P];

// ---------------- helpers ----------------
__device__ __forceinline__ unsigned f2tf32(float f) {
    unsigned u;
    asm("cvt.rna.tf32.f32 %0, %1;" : "=r"(u) : "f"(f));
    return u;
}
__device__ __forceinline__ float ex2f(float x) {
    float y;
    asm("ex2.approx.f32 %0, %1;" : "=f"(y) : "f"(x));
    return y;
}
__device__ __forceinline__ void mma_tf32(float c[4], const unsigned a[4], const unsigned b[2]) {
    asm volatile(
        "mma.sync.aligned.m16n8k8.row.col.f32.tf32.tf32.f32 "
        "{%0,%1,%2,%3}, {%4,%5,%6,%7}, {%8,%9}, {%0,%1,%2,%3};"
        : "+f"(c[0]), "+f"(c[1]), "+f"(c[2]), "+f"(c[3])
        : "r"(a[0]), "r"(a[1]), "r"(a[2]), "r"(a[3]), "r"(b[0]), "r"(b[1]));
}
__device__ __forceinline__ void cp16(float* s, const float* g, int bytes) {
    unsigned sa = (unsigned)__cvta_generic_to_shared(s);
    asm volatile("cp.async.cg.shared.global [%0], [%1], 16, %2;\n"
                 :: "r"(sa), "l"(g), "r"(bytes));
}
__device__ __forceinline__ void cp_commit() { asm volatile("cp.async.commit_group;"); }
template<int NN> __device__ __forceinline__ void cp_wait() {
    asm volatile("cp.async.wait_group %0;" :: "n"(NN));
}

// ---------------- LayerNorm ----------------
__global__ void ln_kernel(const float* __restrict__ x,
                          const float* __restrict__ gamma,
                          const float* __restrict__ beta,
                          float* __restrict__ out)
{
    int row = blockIdx.x;
    int tid = threadIdx.x;
    const float* xr = x + (size_t)row * DMODEL;
    float v0 = xr[tid];
    float v1 = xr[tid + 256];
    float s  = v0 + v1;
    float ss = v0 * v0 + v1 * v1;

    __shared__ float shs[8], shss[8];
    #pragma unroll
    for (int o = 16; o > 0; o >>= 1) {
        s  += __shfl_down_sync(0xffffffffu, s,  o);
        ss += __shfl_down_sync(0xffffffffu, ss, o);
    }
    if ((tid & 31) == 0) { shs[tid >> 5] = s; shss[tid >> 5] = ss; }
    __syncthreads();
    if (tid < 8) {
        s = shs[tid]; ss = shss[tid];
        #pragma unroll
        for (int o = 4; o > 0; o >>= 1) {
            s  += __shfl_down_sync(0xffu, s,  o);
            ss += __shfl_down_sync(0xffu, ss, o);
        }
        if (tid == 0) { shs[0] = s; shss[0] = ss; }
    }
    __syncthreads();
    float mean = shs[0]  * (1.0f / DMODEL);
    float var  = shss[0] * (1.0f / DMODEL) - mean * mean;
    float inv  = rsqrtf(var + 1e-5f);
    float* outr = out + (size_t)row * DMODEL;
    outr[tid]       = (v0 - mean) * inv * gamma[tid]       + beta[tid];
    outr[tid + 256] = (v1 - mean) * inv * gamma[tid + 256] + beta[tid + 256];
}

// ---------------- async-pipelined tf32 GEMM ----------------
// C(MxN) = A(MxK, lda) @ B(KxN, ldb) [+bias][+res]; 128x128 CTA tile, BK=32,
// 2-stage cp.async pipeline. All cp.async addresses 16B-aligned: lda/ldb must
// be multiples of 4 floats.
__device__ __forceinline__ void gemm_stage(
    float (*As)[36], float (*Bs)[136],
    const float* __restrict__ A, const float* __restrict__ B,
    int m0, int n0, int k0, int K, int N, int lda, int ldb, int tid)
{
    #pragma unroll
    for (int i = 0; i < 4; i++) {
        int id  = i * 256 + tid;
        int row = id >> 3, c4 = (id & 7) * 4;
        int kcol = k0 + c4;
        int rem  = K - kcol;
        int bytes = rem >= 4 ? 16 : (rem > 0 ? rem * 4 : 0);
        const float* gp = bytes ? (A + (size_t)(m0 + row) * lda + kcol) : A;
        cp16(&As[row][c4], gp, bytes);
    }
    #pragma unroll
    for (int i = 0; i < 4; i++) {
        int id  = i * 256 + tid;
        int row = id >> 5, c4 = (id & 31) * 4;
        int krow = k0 + row;
        int ncol = n0 + c4;
        int bytes = 0;
        if (krow < K) {
            int rem = N - ncol;
            bytes = rem >= 4 ? 16 : (rem > 0 ? rem * 4 : 0);
        }
        const float* gp = bytes ? (B + (size_t)krow * ldb + ncol) : B;
        cp16(&Bs[row][c4], gp, bytes);
    }
}

template<bool HAS_BIAS, bool HAS_RES>
__global__ void __launch_bounds__(256, 2)
gemm_tf32(const float* __restrict__ A, const float* __restrict__ B,
          const float* __restrict__ bias, const float* __restrict__ res,
          float* __restrict__ C, int M, int N, int K, int lda, int ldb)
{
    __shared__ float As[2][128][36];
    __shared__ float Bs[2][32][136];

    int tid  = threadIdx.x;
    int lane = tid & 31;
    int wid  = tid >> 5;
    int g  = lane >> 2;
    int tg = lane & 3;
    int wm = (wid & 1) * 64;
    int wn = (wid >> 1) * 32;
    int m0 = blockIdx.y * 128, n0 = blockIdx.x * 128;

    float c[4][4][4];
    #pragma unroll
    for (int i = 0; i < 4; i++)
        #pragma unroll
        for (int j = 0; j < 4; j++)
            #pragma unroll
            for (int l = 0; l < 4; l++) c[i][j][l] = 0.0f;

    int T = (K + 31) >> 5;
    gemm_stage(As[0], Bs[0], A, B, m0, n0, 0, K, N, lda, ldb, tid);
    cp_commit();

    for (int kt = 0; kt < T; kt++) {
        int buf = kt & 1;
        if (kt + 1 < T) {
            gemm_stage(As[buf ^ 1], Bs[buf ^ 1], A, B, m0, n0, (kt + 1) * 32,
                       K, N, lda, ldb, tid);
            cp_commit();
            cp_wait<1>();
        } else {
            cp_wait<0>();
        }
        __syncthreads();

        #pragma unroll
        for (int ks = 0; ks < 4; ks++) {
            unsigned a[4][4], b[4][2];
            #pragma unroll
            for (int mf = 0; mf < 4; mf++) {
                int row = wm + mf * 16 + g;
                int col = ks * 8 + tg;
                a[mf][0] = f2tf32(As[buf][row][col]);
                a[mf][1] = f2tf32(As[buf][row + 8][col]);
                a[mf][2] = f2tf32(As[buf][row][col + 4]);
                a[mf][3] = f2tf32(As[buf][row + 8][col + 4]);
            }
            #pragma unroll
            for (int nf = 0; nf < 4; nf++) {
                int col = wn + nf * 8 + g;
                b[nf][0] = f2tf32(Bs[buf][ks * 8 + tg][col]);
                b[nf][1] = f2tf32(Bs[buf][ks * 8 + tg + 4][col]);
            }
            #pragma unroll
            for (int mf = 0; mf < 4; mf++)
                #pragma unroll
                for (int nf = 0; nf < 4; nf++)
                    mma_tf32(c[mf][nf], a[mf], b[nf]);
        }
        __syncthreads();
    }

    #pragma unroll
    for (int mf = 0; mf < 4; mf++) {
        int r0 = m0 + wm + mf * 16 + g;
        #pragma unroll
        for (int nf = 0; nf < 4; nf++) {
            int cc = n0 + wn + nf * 8 + 2 * tg;
            #pragma unroll
            for (int half = 0; half < 2; half++) {
                int r = r0 + half * 8;
                #pragma unroll
                for (int jj = 0; jj < 2; jj++) {
                    int col = cc + jj;
                    if (col < N) {
                        float v = c[mf][nf][half * 2 + jj];
                        if (HAS_BIAS) v += bias[col];
                        if (HAS_RES)  v += res[(size_t)r * N + col];
                        C[(size_t)r * N + col] = v;
                    }
                }
            }
        }
    }
}

// ---------------- QKV split + l2norm + scale + rotary xpos ----------------
__global__ void qkv_rotary_kernel(const float* __restrict__ q_scale,
                                  const float* __restrict__ k_scale)
{
    int lane = threadIdx.x & 31;
    int warp = threadIdx.x >> 5;
    long task = (long)blockIdx.x * 4 + warp;
    int b = (int)(task / ((long)SEQ * NH));
    long rem = task - (long)b * SEQ * NH;
    int n = (int)(rem / NH);
    int h = (int)(rem - (long)n * NH);

    size_t base = ((size_t)b * SEQ + n) * QKVN + (size_t)h * DH;
    float q0 = g_qkv[base + lane],        q1 = g_qkv[base + 32 + lane];
    float k0 = g_qkv[base + 512 + lane],  k1 = g_qkv[base + 512 + 32 + lane];
    float v0 = g_qkv[base + 1024 + lane], v1 = g_qkv[base + 1024 + 32 + lane];

    float sq = q0 * q0 + q1 * q1;
    float sk = k0 * k0 + k1 * k1;
    #pragma unroll
    for (int o = 16; o > 0; o >>= 1) {
        sq += __shfl_xor_sync(0xffffffffu, sq, o);
        sk += __shfl_xor_sync(0xffffffffu, sk, o);
    }
    float qinv = 1.0f / fmaxf(sqrtf(sq), 1e-12f);
    float kinv = 1.0f / fmaxf(sqrtf(sk), 1e-12f);
    q0 = q0 * qinv * q_scale[lane];
    q1 = q1 * qinv * q_scale[lane + 32];
    k0 = k0 * kinv * k_scale[lane];
    k1 = k1 * kinv * k_scale[lane + 32];

    float t    = (float)n;
    float invf = powf(10000.0f, -(float)lane / 32.0f);
    float fr   = t * invf;
    float cs = cosf(fr), sn = sinf(fr);
    float sv = (2.0f * (float)lane + 0.4f * 64.0f) / (1.4f * 64.0f);
    float pw = (t - (float)(SEQ / 2)) / (float)(WSIZE / 2);
    float xs = powf(sv, pw);
    float ixs = 1.0f / xs;

    float qo0 = (q0 * cs - q1 * sn) * xs;
    float qo1 = (q1 * cs + q0 * sn) * xs;
    float ko0 = (k0 * cs - k1 * sn) * ixs;
    float ko1 = (k1 * cs + k0 * sn) * ixs;

    size_t obase = ((size_t)(b * NH + h) * SEQ + n) * DH;
    g_q[obase + lane] = qo0;  g_q[obase + 32 + lane] = qo1;
    g_k[obase + lane] = ko0;  g_k[obase + 32 + lane] = ko1;
    g_v[obase + lane] = v0;   g_v[obase + 32 + lane] = v1;
}

// ---------------- tensor-core local windowed attention ----------------
// CTA = 64 queries x 128 threads (4 warps, 16 q-rows each). 9 key tiles of
// 64 slots. QK^T and PV both via m16n8k8 tf32 mma. K,V in natural [key][dim]
// smem layout; row.col B-fragment indexing supplies the transpose; the C->A
// fragment layout mismatch for P is absorbed by relabeling keys consistently
// in the P (A) and V (B) fragments.
__global__ void __launch_bounds__(128) attn_kernel()
{
    __shared__ float Ks[64][68];
    __shared__ float Vs[64][68];

    const int tid  = threadIdx.x;
    const int lane = tid & 31;
    const int wq   = tid >> 5;
    const int g    = lane >> 2;
    const int tg   = lane & 3;
    const int qb   = blockIdx.x;
    const int bh   = blockIdx.y;
    const int t0   = qb * 64;
    const int w    = t0 >> 9;
    const int ii0  = t0 & 511;
    const int rstart = (w > 0) ? 0 : ((512 - ii0) >> 6);

    const float QSC = 11.541560327111708f;   // 8 * log2(e)
    unsigned qf[8][4];
    {
        const float* qb0 = g_q + ((size_t)bh * SEQ + t0 + wq * 16) * DH;
        #pragma unroll
        for (int kc = 0; kc < 8; kc++) {
            qf[kc][0] = f2tf32(QSC * qb0[(size_t)g * DH + kc * 8 + tg]);
            qf[kc][1] = f2tf32(QSC * qb0[(size_t)(g + 8) * DH + kc * 8 + tg]);
            qf[kc][2] = f2tf32(QSC * qb0[(size_t)g * DH + kc * 8 + tg + 4]);
            qf[kc][3] = f2tf32(QSC * qb0[(size_t)(g + 8) * DH + kc * 8 + tg + 4]);
        }
    }

    float o[8][4];
    #pragma unroll
    for (int i = 0; i < 8; i++)
        #pragma unroll
        for (int j = 0; j < 4; j++) o[i][j] = 0.0f;
    float d0 = 0.0f, d1 = 0.0f;

    const float* kbase = g_k + (size_t)bh * SEQ * DH;
    const float* vbase = g_v + (size_t)bh * SEQ * DH;

    for (int r = rstart; r <= 8; r++) {
        int kg0 = t0 - 512 + 64 * r;

        #pragma unroll
        for (int i = 0; i < 8; i++) {
            int idx = i * 128 + tid;
            int kk = idx >> 4, d4 = idx & 15;
            size_t off = (size_t)(kg0 + kk) * DH + d4 * 4;
            *(float4*)&Ks[kk][d4 * 4] = *(const float4*)&kbase[off];
            *(float4*)&Vs[kk][d4 * 4] = *(const float4*)&vbase[off];
        }
        __syncthreads();

        float s[8][4];
        #pragma unroll
        for (int i = 0; i < 8; i++)
            #pragma unroll
            for (int j = 0; j < 4; j++) s[i][j] = 0.0f;

        #pragma unroll
        for (int kc = 0; kc < 8; kc++) {
            #pragma unroll
            for (int nf = 0; nf < 8; nf++) {
                unsigned b[2];
                b[0] = f2tf32(Ks[nf * 8 + g][kc * 8 + tg]);
                b[1] = f2tf32(Ks[nf * 8 + g][kc * 8 + tg + 4]);
                mma_tf32(s[nf], qf[kc], b);
            }
        }

        bool lower = (r == 0);
        bool upper = (r == 8);
        int q0r = wq * 16 + g;
        float p[8][4];
        #pragma unroll
        for (int nf = 0; nf < 8; nf++) {
            int j0 = nf * 8 + 2 * tg;
            bool ok0 = true, ok1 = true, ok2 = true, ok3 = true;
            if (lower) {
                ok0 = (j0     >= q0r);
                ok1 = (j0 + 1 >= q0r);
                ok2 = (j0     >= q0r + 8);
                ok3 = (j0 + 1 >= q0r + 8);
            }
            if (upper) {
                ok0 = (j0     <= q0r);
                ok1 = (j0 + 1 <= q0r);
                ok2 = (j0     <= q0r + 8);
                ok3 = (j0 + 1 <= q0r + 8);
            }
            p[nf][0] = ok0 ? ex2f(s[nf][0]) : 0.0f;
            p[nf][1] = ok1 ? ex2f(s[nf][1]) : 0.0f;
            p[nf][2] = ok2 ? ex2f(s[nf][2]) : 0.0f;
            p[nf][3] = ok3 ? ex2f(s[nf][3]) : 0.0f;
            d0 += p[nf][0] + p[nf][1];
            d1 += p[nf][2] + p[nf][3];
        }

        #pragma unroll
        for (int kc = 0; kc < 8; kc++) {
            unsigned a[4];
            a[0] = f2tf32(p[kc][0]);
            a[1] = f2tf32(p[kc][2]);
            a[2] = f2tf32(p[kc][1]);
            a[3] = f2tf32(p[kc][3]);
            #pragma unroll
            for (int nf = 0; nf < 8; nf++) {
                unsigned b[2];
                b[0] = f2tf32(Vs[kc * 8 + 2 * tg][nf * 8 + g]);
                b[1] = f2tf32(Vs[kc * 8 + 2 * tg + 1][nf * 8 + g]);
                mma_tf32(o[nf], a, b);
            }
        }
        __syncthreads();
    }

    d0 += __shfl_xor_sync(0xffffffffu, d0, 1);
    d0 += __shfl_xor_sync(0xffffffffu, d0, 2);
    d1 += __shfl_xor_sync(0xffffffffu, d1, 1);
    d1 += __shfl_xor_sync(0xffffffffu, d1, 2);
    float i0 = 1.0f / d0, i1 = 1.0f / d1;

    int b = bh >> 3, h = bh & 7;
    int row0 = t0 + wq * 16 + g;
    float* ob = g_o + (size_t)b * SEQ * DMODEL + h * DH;
    #pragma unroll
    for (int nf = 0; nf < 8; nf++) {
        int col = nf * 8 + 2 * tg;
        float2 lo = make_float2(o[nf][0] * i0, o[nf][1] * i0);
        float2 hi = make_float2(o[nf][2] * i1, o[nf][3] * i1);
        *(float2*)&ob[(size_t)row0 * DMODEL + col]       = lo;
        *(float2*)&ob[(size_t)(row0 + 8) * DMODEL + col] = hi;
    }
}

// ---------------- gated GELU (writes padded-stride gate) ----------------
__global__ void geglu_kernel()
{
    long idx = (long)blockIdx.x * blockDim.x + threadIdx.x;
    long total = (long)BNROWS * HID;
    if (idx >= total) return;
    long r = idx / HID;
    int  c = (int)(idx - r * HID);
    float a  = g_u[r * HID2 + c];
    float gt = g_u[r * HID2 + HID + c];
    float ge = 0.5f * gt * (1.0f + erff(gt * 0.70710678118654752f));
    g_gate[r * HIDP + c] = a * ge;
}

// ---------------- launch ----------------
extern "C" void kernel_launch(void* const* d_in, const int* in_sizes, int n_in,
                              void* d_out, int out_size)
{
    const float* x     = (const float*)d_in[0];
    const float* ln1g  = (const float*)d_in[1];
    const float* ln1b  = (const float*)d_in[2];
    const float* Wqkv  = (const float*)d_in[3];
    const float* qsc   = (const float*)d_in[4];
    const float* ksc   = (const float*)d_in[5];
    const float* Wout  = (const float*)d_in[6];
    const float* ln2g  = (const float*)d_in[7];
    const float* ln2b  = (const float*)d_in[8];
    const float* W1    = (const float*)d_in[9];
    const float* b1    = (const float*)d_in[10];
    const float* W2    = (const float*)d_in[11];
    const float* b2    = (const float*)d_in[12];
    float* out = (float*)d_out;

    float *ph, *pqkv, *po, *px1, *pu, *pg, *pw1p;
    cudaGetSymbolAddress((void**)&ph,   g_h);
    cudaGetSymbolAddress((void**)&pqkv, g_qkv);
    cudaGetSymbolAddress((void**)&po,   g_o);
    cudaGetSymbolAddress((void**)&px1,  g_x1);
    cudaGetSymbolAddress((void**)&pu,   g_u);
    cudaGetSymbolAddress((void**)&pg,   g_gate);
    cudaGetSymbolAddress((void**)&pw1p, g_W1p);

    // 0) repack W1 into 16B-aligned row stride (graph-capturable async memcpy)
    cudaMemcpy2DAsync(pw1p, (size_t)W1P * sizeof(float),
                      W1,   (size_t)HID2 * sizeof(float),
                      (size_t)HID2 * sizeof(float), DMODEL,
                      cudaMemcpyDeviceToDevice);

    // 1) LN1
    ln_kernel<<<BNROWS, 256>>>(x, ln1g, ln1b, ph);
    // 2) QKV GEMM
    gemm_tf32<false, false><<<dim3(QKVN / 128, BNROWS / 128), 256>>>(
        ph, Wqkv, nullptr, nullptr, pqkv, BNROWS, QKVN, DMODEL, DMODEL, QKVN);
    // 3) split + l2norm + rotary xpos
    qkv_rotary_kernel<<<(BATCH * SEQ * NH) / 4, 128>>>(qsc, ksc);
    // 4) tensor-core local attention
    attn_kernel<<<dim3(SEQ / 64, BHEADS), 128>>>();
    // 5) out projection + residual
    gemm_tf32<false, true><<<dim3(DMODEL / 128, BNROWS / 128), 256>>>(
        po, Wout, nullptr, x, px1, BNROWS, DMODEL, DMODEL, DMODEL, DMODEL);
    // 6) LN2
    ln_kernel<<<BNROWS, 256>>>(px1, ln2g, ln2b, ph);
    // 7) FF1 (B = padded W1 copy)
    gemm_tf32<true, false><<<dim3((HID2 + 127) / 128, BNROWS / 128), 256>>>(
        ph, pw1p, b1, nullptr, pu, BNROWS, HID2, DMODEL, DMODEL, W1P);
    // 8) gated gelu -> padded-stride gate
    {
        long total = (long)BNROWS * HID;
        int blocks = (int)((total + 255) / 256);
        geglu_kernel<<<blocks, 256>>>();
    }
    // 9) FF2 + residual -> out (A = padded gate, lda=HIDP)
    gemm_tf32<true, true><<<dim3(DMODEL / 128, BNROWS / 128), 256>>>(
        pg, W2, b2, px1, out, BNROWS, DMODEL, HID, HIDP, DMODEL);
}

// round 5
// speedup vs baseline: 3.6714x; 1.1734x over previous
#include <cuda_runtime.h>
#include <math.h>

// ---------------- problem constants ----------------
#define BATCH   2
#define SEQ     8192
#define DMODEL  512
#define NH      8
#define DH      64
#define BHEADS  16
#define BNROWS  16384
#define QKVN    1536
#define HID     1365
#define HID2    2730
#define HIDP    1368   // padded gate stride (16B-aligned rows)
#define W1P     2732   // padded W1 stride (16B-aligned rows)
#define WSIZE   512

// ---------------- scratch buffers ----------------
__device__ float g_h    [(size_t)BNROWS * DMODEL];
__device__ float g_qkv  [(size_t)BNROWS * QKVN];
__device__ float g_q    [(size_t)BHEADS * SEQ * DH];
__device__ float g_k    [(size_t)BHEADS * SEQ * DH];
__device__ float g_v    [(size_t)BHEADS * SEQ * DH];
__device__ float g_o    [(size_t)BNROWS * DMODEL];
__device__ float g_x1   [(size_t)BNROWS * DMODEL];
__device__ float g_u    [(size_t)BNROWS * HID2];
__device__ float g_gate [(size_t)BNROWS * HIDP];
__device__ float g_W1p  [(size_t)DMODEL * W1P];
__device__ float g_Wqkvc[(size_t)DMODEL * QKVN];
__device__ float g_Woutc[(size_t)DMODEL * DMODEL];
__device__ float g_W2c  [(size_t)HID * DMODEL];

// ---------------- helpers ----------------
__device__ __forceinline__ unsigned f2tf32(float f) {
    unsigned u;
    asm("cvt.rna.tf32.f32 %0, %1;" : "=r"(u) : "f"(f));
    return u;
}
__device__ __forceinline__ float tf32r(float f) {     // tf32-rounded fp32 value
    return __uint_as_float(f2tf32(f));
}
__device__ __forceinline__ float ex2f(float x) {
    float y;
    asm("ex2.approx.f32 %0, %1;" : "=f"(y) : "f"(x));
    return y;
}
__device__ __forceinline__ void mma_tf32(float c[4], const unsigned a[4], const unsigned b[2]) {
    asm volatile(
        "mma.sync.aligned.m16n8k8.row.col.f32.tf32.tf32.f32 "
        "{%0,%1,%2,%3}, {%4,%5,%6,%7}, {%8,%9}, {%0,%1,%2,%3};"
        : "+f"(c[0]), "+f"(c[1]), "+f"(c[2]), "+f"(c[3])
        : "r"(a[0]), "r"(a[1]), "r"(a[2]), "r"(a[3]), "r"(b[0]), "r"(b[1]));
}
__device__ __forceinline__ void cp16(float* s, const float* g, int bytes) {
    unsigned sa = (unsigned)__cvta_generic_to_shared(s);
    asm volatile("cp.async.cg.shared.global [%0], [%1], 16, %2;\n"
                 :: "r"(sa), "l"(g), "r"(bytes));
}
__device__ __forceinline__ void cp_commit() { asm volatile("cp.async.commit_group;"); }
template<int NN> __device__ __forceinline__ void cp_wait() {
    asm volatile("cp.async.wait_group %0;" :: "n"(NN));
}

// ---------------- weight tf32 pre-rounding ----------------
__global__ void cvt_kernel(const float* __restrict__ src, float* __restrict__ dst, int n)
{
    int i = blockIdx.x * 256 + threadIdx.x;
    if (i < n) dst[i] = tf32r(src[i]);
}
__global__ void cvt_w1_kernel(const float* __restrict__ W1)
{
    int i = blockIdx.x * 256 + threadIdx.x;
    if (i < DMODEL * HID2) {
        int r = i / HID2, c = i - r * HID2;
        g_W1p[(size_t)r * W1P + c] = tf32r(W1[i]);
    }
}

// ---------------- LayerNorm (emits tf32-rounded values) ----------------
__global__ void ln_kernel(const float* __restrict__ x,
                          const float* __restrict__ gamma,
                          const float* __restrict__ beta,
                          float* __restrict__ out)
{
    int row = blockIdx.x;
    int tid = threadIdx.x;
    const float* xr = x + (size_t)row * DMODEL;
    float v0 = xr[tid];
    float v1 = xr[tid + 256];
    float s  = v0 + v1;
    float ss = v0 * v0 + v1 * v1;

    __shared__ float shs[8], shss[8];
    #pragma unroll
    for (int o = 16; o > 0; o >>= 1) {
        s  += __shfl_down_sync(0xffffffffu, s,  o);
        ss += __shfl_down_sync(0xffffffffu, ss, o);
    }
    if ((tid & 31) == 0) { shs[tid >> 5] = s; shss[tid >> 5] = ss; }
    __syncthreads();
    if (tid < 8) {
        s = shs[tid]; ss = shss[tid];
        #pragma unroll
        for (int o = 4; o > 0; o >>= 1) {
            s  += __shfl_down_sync(0xffu, s,  o);
            ss += __shfl_down_sync(0xffu, ss, o);
        }
        if (tid == 0) { shs[0] = s; shss[0] = ss; }
    }
    __syncthreads();
    float mean = shs[0]  * (1.0f / DMODEL);
    float var  = shss[0] * (1.0f / DMODEL) - mean * mean;
    float inv  = rsqrtf(var + 1e-5f);
    float* outr = out + (size_t)row * DMODEL;
    outr[tid]       = tf32r((v0 - mean) * inv * gamma[tid]       + beta[tid]);
    outr[tid + 256] = tf32r((v1 - mean) * inv * gamma[tid + 256] + beta[tid + 256]);
}

// ---------------- async-pipelined tf32 GEMM (pre-rounded inputs) ----------------
__device__ __forceinline__ void gemm_stage(
    float (*As)[36], float (*Bs)[136],
    const float* __restrict__ A, const float* __restrict__ B,
    int m0, int n0, int k0, int K, int N, int lda, int ldb, int tid)
{
    #pragma unroll
    for (int i = 0; i < 4; i++) {
        int id  = i * 256 + tid;
        int row = id >> 3, c4 = (id & 7) * 4;
        int kcol = k0 + c4;
        int rem  = K - kcol;
        int bytes = rem >= 4 ? 16 : (rem > 0 ? rem * 4 : 0);
        const float* gp = bytes ? (A + (size_t)(m0 + row) * lda + kcol) : A;
        cp16(&As[row][c4], gp, bytes);
    }
    #pragma unroll
    for (int i = 0; i < 4; i++) {
        int id  = i * 256 + tid;
        int row = id >> 5, c4 = (id & 31) * 4;
        int krow = k0 + row;
        int ncol = n0 + c4;
        int bytes = 0;
        if (krow < K) {
            int rem = N - ncol;
            bytes = rem >= 4 ? 16 : (rem > 0 ? rem * 4 : 0);
        }
        const float* gp = bytes ? (B + (size_t)krow * ldb + ncol) : B;
        cp16(&Bs[row][c4], gp, bytes);
    }
}

template<bool HAS_BIAS, bool HAS_RES>
__global__ void __launch_bounds__(256, 2)
gemm_tf32(const float* __restrict__ A, const float* __restrict__ B,
          const float* __restrict__ bias, const float* __restrict__ res,
          float* __restrict__ C, int M, int N, int K, int lda, int ldb)
{
    __shared__ float As[2][128][36];
    __shared__ float Bs[2][32][136];

    int tid  = threadIdx.x;
    int lane = tid & 31;
    int wid  = tid >> 5;
    int g  = lane >> 2;
    int tg = lane & 3;
    int wm = (wid & 1) * 64;
    int wn = (wid >> 1) * 32;
    int m0 = blockIdx.y * 128, n0 = blockIdx.x * 128;

    float c[4][4][4];
    #pragma unroll
    for (int i = 0; i < 4; i++)
        #pragma unroll
        for (int j = 0; j < 4; j++)
            #pragma unroll
            for (int l = 0; l < 4; l++) c[i][j][l] = 0.0f;

    int T = (K + 31) >> 5;
    gemm_stage(As[0], Bs[0], A, B, m0, n0, 0, K, N, lda, ldb, tid);
    cp_commit();

    for (int kt = 0; kt < T; kt++) {
        int buf = kt & 1;
        if (kt + 1 < T) {
            gemm_stage(As[buf ^ 1], Bs[buf ^ 1], A, B, m0, n0, (kt + 1) * 32,
                       K, N, lda, ldb, tid);
            cp_commit();
            cp_wait<1>();
        } else {
            cp_wait<0>();
        }
        __syncthreads();

        #pragma unroll
        for (int ks = 0; ks < 4; ks++) {
            unsigned a[4][4], b[4][2];
            #pragma unroll
            for (int mf = 0; mf < 4; mf++) {
                int row = wm + mf * 16 + g;
                int col = ks * 8 + tg;
                a[mf][0] = __float_as_uint(As[buf][row][col]);
                a[mf][1] = __float_as_uint(As[buf][row + 8][col]);
                a[mf][2] = __float_as_uint(As[buf][row][col + 4]);
                a[mf][3] = __float_as_uint(As[buf][row + 8][col + 4]);
            }
            #pragma unroll
            for (int nf = 0; nf < 4; nf++) {
                int col = wn + nf * 8 + g;
                b[nf][0] = __float_as_uint(Bs[buf][ks * 8 + tg][col]);
                b[nf][1] = __float_as_uint(Bs[buf][ks * 8 + tg + 4][col]);
            }
            #pragma unroll
            for (int mf = 0; mf < 4; mf++)
                #pragma unroll
                for (int nf = 0; nf < 4; nf++)
                    mma_tf32(c[mf][nf], a[mf], b[nf]);
        }
        __syncthreads();
    }

    #pragma unroll
    for (int mf = 0; mf < 4; mf++) {
        int r0 = m0 + wm + mf * 16 + g;
        #pragma unroll
        for (int nf = 0; nf < 4; nf++) {
            int col = n0 + wn + nf * 8 + 2 * tg;
            if (col < N) {                    // N is even -> col+1 < N too
                #pragma unroll
                for (int half = 0; half < 2; half++) {
                    int r = r0 + half * 8;
                    float2 v = make_float2(c[mf][nf][half * 2],
                                           c[mf][nf][half * 2 + 1]);
                    if (HAS_BIAS) { v.x += bias[col]; v.y += bias[col + 1]; }
                    if (HAS_RES) {
                        float2 rr = *(const float2*)&res[(size_t)r * N + col];
                        v.x += rr.x; v.y += rr.y;
                    }
                    *(float2*)&C[(size_t)r * N + col] = v;
                }
            }
        }
    }
}

// ---------------- QKV split + l2norm + scale + rotary xpos ----------------
// Emits tf32-rounded q (pre-scaled by 8*log2e), k, v.
__global__ void qkv_rotary_kernel(const float* __restrict__ q_scale,
                                  const float* __restrict__ k_scale)
{
    int lane = threadIdx.x & 31;
    int warp = threadIdx.x >> 5;
    long task = (long)blockIdx.x * 4 + warp;
    int b = (int)(task / ((long)SEQ * NH));
    long rem = task - (long)b * SEQ * NH;
    int n = (int)(rem / NH);
    int h = (int)(rem - (long)n * NH);

    size_t base = ((size_t)b * SEQ + n) * QKVN + (size_t)h * DH;
    float q0 = g_qkv[base + lane],        q1 = g_qkv[base + 32 + lane];
    float k0 = g_qkv[base + 512 + lane],  k1 = g_qkv[base + 512 + 32 + lane];
    float v0 = g_qkv[base + 1024 + lane], v1 = g_qkv[base + 1024 + 32 + lane];

    float sq = q0 * q0 + q1 * q1;
    float sk = k0 * k0 + k1 * k1;
    #pragma unroll
    for (int o = 16; o > 0; o >>= 1) {
        sq += __shfl_xor_sync(0xffffffffu, sq, o);
        sk += __shfl_xor_sync(0xffffffffu, sk, o);
    }
    float qinv = 1.0f / fmaxf(sqrtf(sq), 1e-12f);
    float kinv = 1.0f / fmaxf(sqrtf(sk), 1e-12f);
    q0 = q0 * qinv * q_scale[lane];
    q1 = q1 * qinv * q_scale[lane + 32];
    k0 = k0 * kinv * k_scale[lane];
    k1 = k1 * kinv * k_scale[lane + 32];

    float t    = (float)n;
    // 10000^(-lane/32) = 2^(-lane * log2(10000)/32)
    float invf = exp2f((float)lane * (-13.287712379549449f / 32.0f));
    float fr   = t * invf;
    float cs = cosf(fr), sn = sinf(fr);
    float sv = (2.0f * (float)lane + 0.4f * 64.0f) / (1.4f * 64.0f);
    float pw = (t - (float)(SEQ / 2)) / (float)(WSIZE / 2);
    float xs = exp2f(pw * log2f(sv));
    float ixs = 1.0f / xs;

    const float QSC = 11.541560327111708f;   // 8 * log2(e)
    float qo0 = (q0 * cs - q1 * sn) * xs;
    float qo1 = (q1 * cs + q0 * sn) * xs;
    float ko0 = (k0 * cs - k1 * sn) * ixs;
    float ko1 = (k1 * cs + k0 * sn) * ixs;

    size_t obase = ((size_t)(b * NH + h) * SEQ + n) * DH;
    g_q[obase + lane]      = tf32r(QSC * qo0);
    g_q[obase + 32 + lane] = tf32r(QSC * qo1);
    g_k[obase + lane]      = tf32r(ko0);
    g_k[obase + 32 + lane] = tf32r(ko1);
    g_v[obase + lane]      = tf32r(v0);
    g_v[obase + 32 + lane] = tf32r(v1);
}

// ---------------- tensor-core local windowed attention ----------------
// CTA = 128 queries x 256 threads (8 warps, 16 q-rows each); all queries in
// one CTA share the same window. 10 key tiles of 64 slots, cp.async
// double-buffered. Inputs are pre-rounded tf32 bit patterns -> no cvt in the
// hot loop. Generic 2-comparison mask per cell.
__device__ __forceinline__ void attn_stage(
    float (*Ks)[68], float (*Vs)[68],
    const float* kbase, const float* vbase, int kg0, int tid)
{
    #pragma unroll
    for (int i = 0; i < 4; i++) {
        int idx = i * 256 + tid;
        int kk = idx >> 4, d4 = idx & 15;
        size_t off = (size_t)(kg0 + kk) * DH + d4 * 4;
        cp16(&Ks[kk][d4 * 4], kbase + off, 16);
        cp16(&Vs[kk][d4 * 4], vbase + off, 16);
    }
    cp_commit();
}

__global__ void __launch_bounds__(256) attn_kernel()
{
    __shared__ float Ks[2][64][68];
    __shared__ float Vs[2][64][68];

    const int tid  = threadIdx.x;
    const int lane = tid & 31;
    const int wq   = tid >> 5;            // 0..7
    const int g    = lane >> 2;
    const int tg   = lane & 3;
    const int qb   = blockIdx.x;          // 0..63
    const int bh   = blockIdx.y;          // 0..15
    const int t0   = qb * 128;
    const int w    = t0 >> 9;
    const int rstart = (w > 0) ? 0 : ((512 - (t0 & 511)) >> 6);

    // Q fragments: already scaled + tf32-rounded in memory
    unsigned qf[8][4];
    {
        const float* qb0 = g_q + ((size_t)bh * SEQ + t0 + wq * 16) * DH;
        #pragma unroll
        for (int kc = 0; kc < 8; kc++) {
            qf[kc][0] = __float_as_uint(qb0[(size_t)g * DH + kc * 8 + tg]);
            qf[kc][1] = __float_as_uint(qb0[(size_t)(g + 8) * DH + kc * 8 + tg]);
            qf[kc][2] = __float_as_uint(qb0[(size_t)g * DH + kc * 8 + tg + 4]);
            qf[kc][3] = __float_as_uint(qb0[(size_t)(g + 8) * DH + kc * 8 + tg + 4]);
        }
    }

    float o[8][4];
    #pragma unroll
    for (int i = 0; i < 8; i++)
        #pragma unroll
        for (int j = 0; j < 4; j++) o[i][j] = 0.0f;
    float d0 = 0.0f, d1 = 0.0f;

    const float* kbase = g_k + (size_t)bh * SEQ * DH;
    const float* vbase = g_v + (size_t)bh * SEQ * DH;

    attn_stage(Ks[0], Vs[0], kbase, vbase, t0 - 512 + 64 * rstart, tid);

    const int q0r = wq * 16 + g;          // query row (0..127) of c0/c1

    for (int r = rstart; r <= 9; r++) {
        int buf = (r - rstart) & 1;
        if (r < 9) {
            attn_stage(Ks[buf ^ 1], Vs[buf ^ 1], kbase, vbase,
                       t0 - 512 + 64 * (r + 1), tid);
            cp_wait<1>();
        } else {
            cp_wait<0>();
        }
        __syncthreads();

        // S = Qscaled @ K^T
        float s[8][4];
        #pragma unroll
        for (int i = 0; i < 8; i++)
            #pragma unroll
            for (int j = 0; j < 4; j++) s[i][j] = 0.0f;

        #pragma unroll
        for (int kc = 0; kc < 8; kc++) {
            #pragma unroll
            for (int nf = 0; nf < 8; nf++) {
                unsigned b[2];
                b[0] = __float_as_uint(Ks[buf][nf * 8 + g][kc * 8 + tg]);
                b[1] = __float_as_uint(Ks[buf][nf * 8 + g][kc * 8 + tg + 4]);
                mma_tf32(s[nf], qf[kc], b);
            }
        }

        // mask + exp2: key jrel = 64r - 512 + slot; allowed iff
        // q0r-512 <= jrel <= q0r
        float p[8][4];
        #pragma unroll
        for (int nf = 0; nf < 8; nf++) {
            int j0  = nf * 8 + 2 * tg;
            int jr0 = 64 * r - 512 + j0;
            int jr1 = jr0 + 1;
            bool ok0 = (jr0 <= q0r)     && (jr0 >= q0r - 512);
            bool ok1 = (jr1 <= q0r)     && (jr1 >= q0r - 512);
            bool ok2 = (jr0 <= q0r + 8) && (jr0 >= q0r - 504);
            bool ok3 = (jr1 <= q0r + 8) && (jr1 >= q0r - 504);
            p[nf][0] = ok0 ? ex2f(s[nf][0]) : 0.0f;
            p[nf][1] = ok1 ? ex2f(s[nf][1]) : 0.0f;
            p[nf][2] = ok2 ? ex2f(s[nf][2]) : 0.0f;
            p[nf][3] = ok3 ? ex2f(s[nf][3]) : 0.0f;
            d0 += p[nf][0] + p[nf][1];
            d1 += p[nf][2] + p[nf][3];
        }

        // O += P @ V  (consistent key relabeling in P(A) and V(B) fragments)
        #pragma unroll
        for (int kc = 0; kc < 8; kc++) {
            unsigned a[4];
            a[0] = f2tf32(p[kc][0]);
            a[1] = f2tf32(p[kc][2]);
            a[2] = f2tf32(p[kc][1]);
            a[3] = f2tf32(p[kc][3]);
            #pragma unroll
            for (int nf = 0; nf < 8; nf++) {
                unsigned b[2];
                b[0] = __float_as_uint(Vs[buf][kc * 8 + 2 * tg][nf * 8 + g]);
                b[1] = __float_as_uint(Vs[buf][kc * 8 + 2 * tg + 1][nf * 8 + g]);
                mma_tf32(o[nf], a, b);
            }
        }
        __syncthreads();
    }

    d0 += __shfl_xor_sync(0xffffffffu, d0, 1);
    d0 += __shfl_xor_sync(0xffffffffu, d0, 2);
    d1 += __shfl_xor_sync(0xffffffffu, d1, 1);
    d1 += __shfl_xor_sync(0xffffffffu, d1, 2);
    float i0 = 1.0f / d0, i1 = 1.0f / d1;

    int b = bh >> 3, h = bh & 7;
    int row0 = t0 + wq * 16 + g;
    float* ob = g_o + (size_t)b * SEQ * DMODEL + h * DH;
    #pragma unroll
    for (int nf = 0; nf < 8; nf++) {
        int col = nf * 8 + 2 * tg;
        float2 lo = make_float2(tf32r(o[nf][0] * i0), tf32r(o[nf][1] * i0));
        float2 hi = make_float2(tf32r(o[nf][2] * i1), tf32r(o[nf][3] * i1));
        *(float2*)&ob[(size_t)row0 * DMODEL + col]       = lo;
        *(float2*)&ob[(size_t)(row0 + 8) * DMODEL + col] = hi;
    }
}

// ---------------- gated GELU (emits tf32-rounded, padded stride) ----------------
__global__ void geglu_kernel()
{
    long idx = (long)blockIdx.x * blockDim.x + threadIdx.x;
    long total = (long)BNROWS * HID;
    if (idx >= total) return;
    long r = idx / HID;
    int  c = (int)(idx - r * HID);
    float a  = g_u[r * HID2 + c];
    float gt = g_u[r * HID2 + HID + c];
    float ge = 0.5f * gt * (1.0f + erff(gt * 0.70710678118654752f));
    g_gate[r * HIDP + c] = tf32r(a * ge);
}

// ---------------- launch ----------------
extern "C" void kernel_launch(void* const* d_in, const int* in_sizes, int n_in,
                              void* d_out, int out_size)
{
    const float* x     = (const float*)d_in[0];
    const float* ln1g  = (const float*)d_in[1];
    const float* ln1b  = (const float*)d_in[2];
    const float* Wqkv  = (const float*)d_in[3];
    const float* qsc   = (const float*)d_in[4];
    const float* ksc   = (const float*)d_in[5];
    const float* Wout  = (const float*)d_in[6];
    const float* ln2g  = (const float*)d_in[7];
    const float* ln2b  = (const float*)d_in[8];
    const float* W1    = (const float*)d_in[9];
    const float* b1    = (const float*)d_in[10];
    const float* W2    = (const float*)d_in[11];
    const float* b2    = (const float*)d_in[12];
    float* out = (float*)d_out;

    float *ph, *pqkv, *po, *px1, *pu, *pg, *pw1p, *pwqkv, *pwout, *pw2;
    cudaGetSymbolAddress((void**)&ph,    g_h);
    cudaGetSymbolAddress((void**)&pqkv,  g_qkv);
    cudaGetSymbolAddress((void**)&po,    g_o);
    cudaGetSymbolAddress((void**)&px1,   g_x1);
    cudaGetSymbolAddress((void**)&pu,    g_u);
    cudaGetSymbolAddress((void**)&pg,    g_gate);
    cudaGetSymbolAddress((void**)&pw1p,  g_W1p);
    cudaGetSymbolAddress((void**)&pwqkv, g_Wqkvc);
    cudaGetSymbolAddress((void**)&pwout, g_Woutc);
    cudaGetSymbolAddress((void**)&pw2,   g_W2c);

    // 0) weight tf32 pre-rounding (+ W1 alignment repack)
    {
        int n;
        n = DMODEL * QKVN;  cvt_kernel<<<(n + 255) / 256, 256>>>(Wqkv, pwqkv, n);
        n = DMODEL * DMODEL;cvt_kernel<<<(n + 255) / 256, 256>>>(Wout, pwout, n);
        n = HID * DMODEL;   cvt_kernel<<<(n + 255) / 256, 256>>>(W2, pw2, n);
        n = DMODEL * HID2;  cvt_w1_kernel<<<(n + 255) / 256, 256>>>(W1);
    }

    // 1) LN1
    ln_kernel<<<BNROWS, 256>>>(x, ln1g, ln1b, ph);
    // 2) QKV GEMM
    gemm_tf32<false, false><<<dim3(QKVN / 128, BNROWS / 128), 256>>>(
        ph, pwqkv, nullptr, nullptr, pqkv, BNROWS, QKVN, DMODEL, DMODEL, QKVN);
    // 3) split + l2norm + rotary xpos
    qkv_rotary_kernel<<<(BATCH * SEQ * NH) / 4, 128>>>(qsc, ksc);
    // 4) tensor-core local attention (128 queries / CTA, double-buffered)
    attn_kernel<<<dim3(SEQ / 128, BHEADS), 256>>>();
    // 5) out projection + residual
    gemm_tf32<false, true><<<dim3(DMODEL / 128, BNROWS / 128), 256>>>(
        po, pwout, nullptr, x, px1, BNROWS, DMODEL, DMODEL, DMODEL, DMODEL);
    // 6) LN2
    ln_kernel<<<BNROWS, 256>>>(px1, ln2g, ln2b, ph);
    // 7) FF1 (B = padded + rounded W1)
    gemm_tf32<true, false><<<dim3((HID2 + 127) / 128, BNROWS / 128), 256>>>(
        ph, pw1p, b1, nullptr, pu, BNROWS, HID2, DMODEL, DMODEL, W1P);
    // 8) gated gelu
    {
        long total = (long)BNROWS * HID;
        int blocks = (int)((total + 255) / 256);
        geglu_kernel<<<blocks, 256>>>();
    }
    // 9) FF2 + residual -> out
    gemm_tf32<true, true><<<dim3(DMODEL / 128, BNROWS / 128), 256>>>(
        pg, pw2, b2, px1, out, BNROWS, DMODEL, HID, HIDP, DMODEL);
}